// round 2
// baseline (speedup 1.0000x reference)
#include <cuda_runtime.h>
#include <math.h>

#define NN 50000
#define EE 800000
#define EPE 850000   /* EE + NN self loops */

// ---------------- scratch (static device memory; no runtime allocation) ---
__device__ int    g_cnt[NN];
__device__ int    g_cur[NN];
__device__ int    g_off[NN + 1];
__device__ int    g_srcs[EPE];
__device__ __align__(16) float2 g_as[NN];
__device__ __align__(16) float2 g_ad[NN];
__device__ __align__(16) float  g_ps[2 * 128];
__device__ __align__(16) float  g_pd[2 * 128];
__device__ __align__(16) float  g_Wc[256 * 128];
__device__ __align__(16) float  g_agg[(size_t)NN * 256];
__device__ __align__(16) float  g_xbuf[(size_t)NN * 128];

// ---------------- CSR build ------------------------------------------------
__global__ void zero_kernel() {
    int i = blockIdx.x * blockDim.x + threadIdx.x;
    if (i < NN) { g_cnt[i] = 0; g_cur[i] = 0; }
}

__global__ void hist_kernel(const int* __restrict__ ei) {
    int i = blockIdx.x * blockDim.x + threadIdx.x;
    if (i >= EPE) return;
    int dst = (i < EE) ? ei[EE + i] : (i - EE);
    dst = min(max(dst, 0), NN - 1);          // harden against dtype surprises
    atomicAdd(&g_cnt[dst], 1);
}

__global__ void scan_kernel() {
    __shared__ int sh[1024];
    int t = threadIdx.x;
    const int C = (NN + 1023) >> 10;   // 49
    int base = t * C;
    int local = 0;
    for (int i = 0; i < C; i++) {
        int idx = base + i;
        if (idx < NN) local += g_cnt[idx];
    }
    sh[t] = local;
    __syncthreads();
    for (int d = 1; d < 1024; d <<= 1) {
        int v = 0;
        if (t >= d) v = sh[t - d];
        __syncthreads();
        sh[t] += v;
        __syncthreads();
    }
    int run = (t == 0) ? 0 : sh[t - 1];
    for (int i = 0; i < C; i++) {
        int idx = base + i;
        if (idx < NN) {
            g_off[idx] = run;
            run += g_cnt[idx];
        }
    }
    if (t == 1023) g_off[NN] = sh[1023];
}

__global__ void scatter_kernel(const int* __restrict__ ei) {
    int i = blockIdx.x * blockDim.x + threadIdx.x;
    if (i >= EPE) return;
    int src, dst;
    if (i < EE) { src = ei[i]; dst = ei[EE + i]; }
    else        { src = i - EE; dst = i - EE; }
    src = min(max(src, 0), NN - 1);
    dst = min(max(dst, 0), NN - 1);
    int pos = g_off[dst] + atomicAdd(&g_cur[dst], 1);
    if (pos >= 0 && pos < EPE) g_srcs[pos] = src;
}

// ---------------- per-layer weight prep ------------------------------------
// p_s[h][k] = sum_j W[k][h*128+j] * att_src[h][j]   (same for p_d)
__global__ void prep_p_kernel(const float* __restrict__ Wl,
                              const float* __restrict__ asl,
                              const float* __restrict__ adl) {
    int h   = blockIdx.x & 1;
    int typ = blockIdx.x >> 1;          // 0 = src, 1 = dst
    int k   = threadIdx.x;              // 0..127
    const float* att = (typ ? adl : asl) + h * 128;
    const float* Wr  = Wl + (size_t)k * 256 + h * 128;
    float sum = 0.f;
#pragma unroll 8
    for (int j = 0; j < 128; j++) sum += Wr[j] * att[j];
    (typ ? g_pd : g_ps)[h * 128 + k] = sum;
}

// Wc[k=h*128+j][c] = W[j][h*128+c]
__global__ void prep_wc_kernel(const float* __restrict__ Wl) {
    int idx = blockIdx.x * blockDim.x + threadIdx.x;   // 0..32767
    int k = idx >> 7, c = idx & 127;
    int h = k >> 7,  j = k & 127;
    g_Wc[idx] = Wl[(size_t)j * 256 + h * 128 + c];
}

// ---------------- alpha = x . p ---------------------------------------------
__global__ void __launch_bounds__(256) alpha_kernel(const float* __restrict__ x) {
    int w = (blockIdx.x * blockDim.x + threadIdx.x) >> 5;
    if (w >= NN) return;
    int lane = threadIdx.x & 31;
    float4 xv = *(const float4*)(x + (size_t)w * 128 + lane * 4);
    float4 p;
    p = *(const float4*)(g_ps + lane * 4);
    float s0 = xv.x * p.x + xv.y * p.y + xv.z * p.z + xv.w * p.w;
    p = *(const float4*)(g_ps + 128 + lane * 4);
    float s1 = xv.x * p.x + xv.y * p.y + xv.z * p.z + xv.w * p.w;
    p = *(const float4*)(g_pd + lane * 4);
    float d0 = xv.x * p.x + xv.y * p.y + xv.z * p.z + xv.w * p.w;
    p = *(const float4*)(g_pd + 128 + lane * 4);
    float d1 = xv.x * p.x + xv.y * p.y + xv.z * p.z + xv.w * p.w;
#pragma unroll
    for (int o = 16; o; o >>= 1) {
        s0 += __shfl_xor_sync(0xffffffffu, s0, o);
        s1 += __shfl_xor_sync(0xffffffffu, s1, o);
        d0 += __shfl_xor_sync(0xffffffffu, d0, o);
        d1 += __shfl_xor_sync(0xffffffffu, d1, o);
    }
    if (lane == 0) {
        g_as[w] = make_float2(s0, s1);
        g_ad[w] = make_float2(d0, d1);
    }
}

// ---------------- edge aggregation (online softmax, warp per node) ---------
__global__ void __launch_bounds__(256) aggregate_kernel(const float* __restrict__ x) {
    int node = (blockIdx.x * blockDim.x + threadIdx.x) >> 5;
    if (node >= NN) return;
    int lane = threadIdx.x & 31;
    int head = lane >> 4;
    int lpos = lane & 15;

    int beg = g_off[node], end = g_off[node + 1];
    float2 adv = g_ad[node];
    float my_ad = head ? adv.y : adv.x;

    float m = -1e30f, s = 0.f;
    float acc[8];
#pragma unroll
    for (int i = 0; i < 8; i++) acc[i] = 0.f;

    const float* xb = x + lpos * 8;

    for (int base = beg; base < end; base += 32) {
        int n = min(32, end - base);
        int sj = 0;
        float2 aj = make_float2(0.f, 0.f);
        if (base + lane < end) {
            sj = g_srcs[base + lane];
            aj = g_as[sj];
        }
        for (int i = 0; i < n; i++) {
            int   src = __shfl_sync(0xffffffffu, sj, i);
            float a0  = __shfl_sync(0xffffffffu, aj.x, i);
            float a1  = __shfl_sync(0xffffffffu, aj.y, i);
            float ev  = (head ? a1 : a0) + my_ad;
            ev = ev > 0.f ? ev : 0.2f * ev;     // leaky_relu

            float4 v0 = *(const float4*)(xb + (size_t)src * 128);
            float4 v1 = *(const float4*)(xb + (size_t)src * 128 + 4);

            float nm = fmaxf(m, ev);
            if (nm > m) {                        // rescale (rare path)
                float cs = __expf(m - nm);
                s *= cs;
#pragma unroll
                for (int q = 0; q < 8; q++) acc[q] *= cs;
                m = nm;
            }
            float w = __expf(ev - m);
            s += w;
            acc[0] += w * v0.x; acc[1] += w * v0.y;
            acc[2] += w * v0.z; acc[3] += w * v0.w;
            acc[4] += w * v1.x; acc[5] += w * v1.y;
            acc[6] += w * v1.z; acc[7] += w * v1.w;
        }
    }
    float inv = 1.f / (s + 1e-16f);
    float* o = g_agg + (size_t)node * 256 + head * 128 + lpos * 8;
    *(float4*)o       = make_float4(acc[0] * inv, acc[1] * inv, acc[2] * inv, acc[3] * inv);
    *(float4*)(o + 4) = make_float4(acc[4] * inv, acc[5] * inv, acc[6] * inv, acc[7] * inv);
}

// ---------------- GEMM  out = 0.5 * agg @ Wc + bias, then row L2 norm -------
__global__ void __launch_bounds__(256) gemm_norm_kernel(const float* __restrict__ bias,
                                                        float* __restrict__ out) {
    __shared__ __align__(16) float As[16][132];
    __shared__ __align__(16) float Bs[16][128];
    const int tid = threadIdx.x;
    const int tx = tid & 15, ty = tid >> 4;
    const int m0 = blockIdx.x * 128;

    float acc[8][8];
#pragma unroll
    for (int i = 0; i < 8; i++)
#pragma unroll
        for (int j = 0; j < 8; j++) acc[i][j] = 0.f;

    for (int kc = 0; kc < 256; kc += 16) {
#pragma unroll
        for (int rep = 0; rep < 2; rep++) {
            int f = tid + rep * 256;
            int m = f >> 2, kq = f & 3;
            int row = m0 + m;
            float4 v = make_float4(0.f, 0.f, 0.f, 0.f);
            if (row < NN) v = *(const float4*)(g_agg + (size_t)row * 256 + kc + kq * 4);
            As[kq * 4 + 0][m] = v.x;
            As[kq * 4 + 1][m] = v.y;
            As[kq * 4 + 2][m] = v.z;
            As[kq * 4 + 3][m] = v.w;

            int k = f >> 5, cq = f & 31;
            *(float4*)&Bs[k][cq * 4] = *(const float4*)(g_Wc + (size_t)(kc + k) * 128 + cq * 4);
        }
        __syncthreads();
#pragma unroll
        for (int k = 0; k < 16; k++) {
            float a[8], b[8];
            *(float4*)(a)     = *(const float4*)&As[k][ty * 8];
            *(float4*)(a + 4) = *(const float4*)&As[k][ty * 8 + 4];
            *(float4*)(b)     = *(const float4*)&Bs[k][tx * 8];
            *(float4*)(b + 4) = *(const float4*)&Bs[k][tx * 8 + 4];
#pragma unroll
            for (int i = 0; i < 8; i++)
#pragma unroll
                for (int j = 0; j < 8; j++) acc[i][j] += a[i] * b[j];
        }
        __syncthreads();
    }

    float bv[8];
    *(float4*)(bv)     = *(const float4*)(bias + tx * 8);
    *(float4*)(bv + 4) = *(const float4*)(bias + tx * 8 + 4);

    float ss[8];
#pragma unroll
    for (int i = 0; i < 8; i++) {
        float sum = 0.f;
#pragma unroll
        for (int j = 0; j < 8; j++) {
            float v = acc[i][j] * 0.5f + bv[j];
            acc[i][j] = v;
            sum += v * v;
        }
        ss[i] = sum;
    }
#pragma unroll
    for (int o = 1; o < 16; o <<= 1)
#pragma unroll
        for (int i = 0; i < 8; i++) ss[i] += __shfl_xor_sync(0xffffffffu, ss[i], o);

#pragma unroll
    for (int i = 0; i < 8; i++) {
        float inv = 1.f / fmaxf(sqrtf(ss[i]), 1e-12f);
#pragma unroll
        for (int j = 0; j < 8; j++) acc[i][j] *= inv;
    }
#pragma unroll
    for (int i = 0; i < 8; i++) {
        int row = m0 + ty * 8 + i;
        if (row < NN) {
            *(float4*)(out + (size_t)row * 128 + tx * 8) =
                make_float4(acc[i][0], acc[i][1], acc[i][2], acc[i][3]);
            *(float4*)(out + (size_t)row * 128 + tx * 8 + 4) =
                make_float4(acc[i][4], acc[i][5], acc[i][6], acc[i][7]);
        }
    }
}

// ---------------- launch ----------------------------------------------------
extern "C" void kernel_launch(void* const* d_in, const int* in_sizes, int n_in,
                              void* d_out, int out_size) {
    const float* x    = (const float*)d_in[0];
    const int*   ei   = (const int*)d_in[1];      // JAX x64 disabled -> int32
    const float* W    = (const float*)d_in[2];
    const float* asrc = (const float*)d_in[3];
    const float* adst = (const float*)d_in[4];
    const float* bias = (const float*)d_in[5];
    float*       out  = (float*)d_out;

    void* xbuf_p = nullptr;
    cudaGetSymbolAddress(&xbuf_p, g_xbuf);
    float* xbuf = (float*)xbuf_p;

    zero_kernel<<<(NN + 255) / 256, 256>>>();
    hist_kernel<<<(EPE + 255) / 256, 256>>>(ei);
    scan_kernel<<<1, 1024>>>();
    scatter_kernel<<<(EPE + 255) / 256, 256>>>(ei);

    for (int l = 0; l < 2; l++) {
        const float* Wl  = W + (size_t)l * 128 * 256;
        const float* asl = asrc + (size_t)l * 256;
        const float* adl = adst + (size_t)l * 256;
        const float* bl  = bias + (size_t)l * 128;
        const float* xin = (l == 0) ? x : xbuf;
        float*       xo  = (l == 0) ? xbuf : out;

        prep_p_kernel<<<4, 128>>>(Wl, asl, adl);
        prep_wc_kernel<<<128, 256>>>(Wl);
        alpha_kernel<<<(NN * 32 + 255) / 256, 256>>>(xin);
        aggregate_kernel<<<(NN * 32 + 255) / 256, 256>>>(xin);
        gemm_norm_kernel<<<(NN + 127) / 128, 256>>>(bl, xo);
    }
}

// round 4
// speedup vs baseline: 1.2987x; 1.2987x over previous
#include <cuda_runtime.h>
#include <cuda_bf16.h>
#include <math.h>
#include <stdint.h>

#define NN 50000
#define EE 800000
#define EPE 850000               /* EE + NN self loops */
#define TILES 391                /* ceil(50000/128) */
#define NPAD (TILES * 128)       /* 50048 */

// ---------------- scratch (static device memory) ---------------------------
__device__ int    g_cnt[NN];
__device__ int    g_cur[NN];
__device__ int    g_off[NN + 1];
__device__ int    g_srcs[EPE];
__device__ __align__(16) float2 g_as[NN];
__device__ __align__(16) float2 g_ad[NN];
__device__ __align__(16) float  g_ps[2 * 128];
__device__ __align__(16) float  g_pd[2 * 128];
__device__ __align__(16) float  g_xbuf[(size_t)NN * 128];
__device__ __align__(16) __nv_bfloat16 g_ah[(size_t)NPAD * 256];  // A hi
__device__ __align__(16) __nv_bfloat16 g_al[(size_t)NPAD * 256];  // A lo
__device__ __align__(16) __nv_bfloat16 g_Wh[128 * 256];           // B hi [n][k]
__device__ __align__(16) __nv_bfloat16 g_Wl[128 * 256];           // B lo

// ---------------- warp MMA helpers (sm_80+ baseline instructions) ----------
__device__ __forceinline__ uint32_t smem_u32(const void* p) {
    uint32_t a;
    asm("{ .reg .u64 t; cvta.to.shared.u64 t, %1; cvt.u32.u64 %0, t; }"
        : "=r"(a) : "l"(p));
    return a;
}
__device__ __forceinline__ void ldsm_x4(uint32_t* r, uint32_t addr) {
    asm volatile("ldmatrix.sync.aligned.m8n8.x4.shared.b16 {%0,%1,%2,%3}, [%4];"
                 : "=r"(r[0]), "=r"(r[1]), "=r"(r[2]), "=r"(r[3]) : "r"(addr));
}
__device__ __forceinline__ void ldsm_x2(uint32_t* r, uint32_t addr) {
    asm volatile("ldmatrix.sync.aligned.m8n8.x2.shared.b16 {%0,%1}, [%2];"
                 : "=r"(r[0]), "=r"(r[1]) : "r"(addr));
}
__device__ __forceinline__ void mma16816(float* c, const uint32_t* a, const uint32_t* b) {
    asm volatile("mma.sync.aligned.m16n8k16.row.col.f32.bf16.bf16.f32 "
                 "{%0,%1,%2,%3}, {%4,%5,%6,%7}, {%8,%9}, {%0,%1,%2,%3};"
                 : "+f"(c[0]), "+f"(c[1]), "+f"(c[2]), "+f"(c[3])
                 : "r"(a[0]), "r"(a[1]), "r"(a[2]), "r"(a[3]),
                   "r"(b[0]), "r"(b[1]));
}

// ---------------- CSR build ------------------------------------------------
__global__ void zero_kernel() {
    int i = blockIdx.x * blockDim.x + threadIdx.x;
    if (i < NN) { g_cnt[i] = 0; g_cur[i] = 0; }
}
__global__ void hist_kernel(const int* __restrict__ ei) {
    int i = blockIdx.x * blockDim.x + threadIdx.x;
    if (i >= EPE) return;
    int dst = (i < EE) ? ei[EE + i] : (i - EE);
    dst = min(max(dst, 0), NN - 1);
    atomicAdd(&g_cnt[dst], 1);
}
__global__ void scan_kernel() {
    __shared__ int sh[1024];
    int t = threadIdx.x;
    const int C = (NN + 1023) >> 10;
    int base = t * C, local = 0;
    for (int i = 0; i < C; i++) { int idx = base + i; if (idx < NN) local += g_cnt[idx]; }
    sh[t] = local;
    __syncthreads();
    for (int d = 1; d < 1024; d <<= 1) {
        int v = 0;
        if (t >= d) v = sh[t - d];
        __syncthreads();
        sh[t] += v;
        __syncthreads();
    }
    int run = (t == 0) ? 0 : sh[t - 1];
    for (int i = 0; i < C; i++) {
        int idx = base + i;
        if (idx < NN) { g_off[idx] = run; run += g_cnt[idx]; }
    }
    if (t == 1023) g_off[NN] = sh[1023];
}
__global__ void scatter_kernel(const int* __restrict__ ei) {
    int i = blockIdx.x * blockDim.x + threadIdx.x;
    if (i >= EPE) return;
    int src, dst;
    if (i < EE) { src = ei[i]; dst = ei[EE + i]; }
    else        { src = i - EE; dst = i - EE; }
    src = min(max(src, 0), NN - 1);
    dst = min(max(dst, 0), NN - 1);
    int pos = g_off[dst] + atomicAdd(&g_cur[dst], 1);
    if (pos >= 0 && pos < EPE) g_srcs[pos] = src;
}

// ---------------- per-layer weight prep ------------------------------------
__global__ void prep_p_kernel(const float* __restrict__ Wl,
                              const float* __restrict__ asl,
                              const float* __restrict__ adl) {
    int h = blockIdx.x & 1, typ = blockIdx.x >> 1, k = threadIdx.x;
    const float* att = (typ ? adl : asl) + h * 128;
    const float* Wr  = Wl + (size_t)k * 256 + h * 128;
    float sum = 0.f;
#pragma unroll 8
    for (int j = 0; j < 128; j++) sum += Wr[j] * att[j];
    (typ ? g_pd : g_ps)[h * 128 + k] = sum;
}

// B[n][k] = 0.5 * W[j][h*128+n], k = h*128+j  (0.5 = head mean, folded in)
__global__ void prep_w_kernel(const float* __restrict__ Wl) {
    int idx = blockIdx.x * blockDim.x + threadIdx.x;   // 0..32767
    int n = idx >> 8, k = idx & 255;
    int h = k >> 7,  j = k & 127;
    float v = 0.5f * Wl[(size_t)j * 256 + h * 128 + n];
    __nv_bfloat16 hi = __float2bfloat16(v);
    g_Wh[idx] = hi;
    g_Wl[idx] = __float2bfloat16(v - __bfloat162float(hi));
}

// ---------------- alpha = x . p ---------------------------------------------
__global__ void __launch_bounds__(256) alpha_kernel(const float* __restrict__ x) {
    int w = (blockIdx.x * blockDim.x + threadIdx.x) >> 5;
    if (w >= NN) return;
    int lane = threadIdx.x & 31;
    float4 xv = *(const float4*)(x + (size_t)w * 128 + lane * 4);
    float4 p;
    p = *(const float4*)(g_ps + lane * 4);
    float s0 = xv.x * p.x + xv.y * p.y + xv.z * p.z + xv.w * p.w;
    p = *(const float4*)(g_ps + 128 + lane * 4);
    float s1 = xv.x * p.x + xv.y * p.y + xv.z * p.z + xv.w * p.w;
    p = *(const float4*)(g_pd + lane * 4);
    float d0 = xv.x * p.x + xv.y * p.y + xv.z * p.z + xv.w * p.w;
    p = *(const float4*)(g_pd + 128 + lane * 4);
    float d1 = xv.x * p.x + xv.y * p.y + xv.z * p.z + xv.w * p.w;
#pragma unroll
    for (int o = 16; o; o >>= 1) {
        s0 += __shfl_xor_sync(0xffffffffu, s0, o);
        s1 += __shfl_xor_sync(0xffffffffu, s1, o);
        d0 += __shfl_xor_sync(0xffffffffu, d0, o);
        d1 += __shfl_xor_sync(0xffffffffu, d1, o);
    }
    if (lane == 0) {
        g_as[w] = make_float2(s0, s1);
        g_ad[w] = make_float2(d0, d1);
    }
}

// ---------------- edge aggregation (online softmax, warp per node) ---------
__device__ __forceinline__ uint32_t pack_split(float a, float b, uint32_t& lo) {
    __nv_bfloat16 ha = __float2bfloat16(a), hb = __float2bfloat16(b);
    __nv_bfloat16 la = __float2bfloat16(a - __bfloat162float(ha));
    __nv_bfloat16 lb = __float2bfloat16(b - __bfloat162float(hb));
    lo = (uint32_t)__bfloat16_as_ushort(la) | ((uint32_t)__bfloat16_as_ushort(lb) << 16);
    return (uint32_t)__bfloat16_as_ushort(ha) | ((uint32_t)__bfloat16_as_ushort(hb) << 16);
}

__global__ void __launch_bounds__(256) aggregate_kernel(const float* __restrict__ x) {
    int node = (blockIdx.x * blockDim.x + threadIdx.x) >> 5;
    if (node >= NN) return;
    int lane = threadIdx.x & 31;
    int head = lane >> 4;
    int lpos = lane & 15;

    int beg = g_off[node], end = g_off[node + 1];
    float2 adv = g_ad[node];
    float my_ad = head ? adv.y : adv.x;

    float m = -1e30f, s = 0.f;
    float acc[8];
#pragma unroll
    for (int i = 0; i < 8; i++) acc[i] = 0.f;

    const float* xb = x + lpos * 8;

    for (int base = beg; base < end; base += 32) {
        int n = min(32, end - base);
        int sj = 0;
        float2 aj = make_float2(0.f, 0.f);
        if (base + lane < end) {
            sj = g_srcs[base + lane];
            aj = g_as[sj];
        }
        for (int i = 0; i < n; i++) {
            int   src = __shfl_sync(0xffffffffu, sj, i);
            float a0  = __shfl_sync(0xffffffffu, aj.x, i);
            float a1  = __shfl_sync(0xffffffffu, aj.y, i);
            float ev  = (head ? a1 : a0) + my_ad;
            ev = ev > 0.f ? ev : 0.2f * ev;

            float4 v0 = *(const float4*)(xb + (size_t)src * 128);
            float4 v1 = *(const float4*)(xb + (size_t)src * 128 + 4);

            float nm = fmaxf(m, ev);
            if (nm > m) {
                float cs = __expf(m - nm);
                s *= cs;
#pragma unroll
                for (int q = 0; q < 8; q++) acc[q] *= cs;
                m = nm;
            }
            float w = __expf(ev - m);
            s += w;
            acc[0] += w * v0.x; acc[1] += w * v0.y;
            acc[2] += w * v0.z; acc[3] += w * v0.w;
            acc[4] += w * v1.x; acc[5] += w * v1.y;
            acc[6] += w * v1.z; acc[7] += w * v1.w;
        }
    }
    float inv = 1.f / (s + 1e-16f);
    uint4 uh, ul;
    uh.x = pack_split(acc[0] * inv, acc[1] * inv, ul.x);
    uh.y = pack_split(acc[2] * inv, acc[3] * inv, ul.y);
    uh.z = pack_split(acc[4] * inv, acc[5] * inv, ul.z);
    uh.w = pack_split(acc[6] * inv, acc[7] * inv, ul.w);
    size_t o = (size_t)node * 256 + head * 128 + lpos * 8;
    *(uint4*)(g_ah + o) = uh;
    *(uint4*)(g_al + o) = ul;
}

// ---------------- HMMA GEMM + bias + row L2 norm ----------------------------
// D[m][n] = sum_k A[m][k]*B[n][k];  A = agg hi/lo, B = 0.5*W hi/lo
// 3-term compensation: Ah*Bh + Ah*Bl + Al*Bh, fp32 accumulate.
// Block: 128x128 tile, 8 warps (2m x 4n), warp tile 64x32.
#define ROWB 80            /* smem row stride in bytes (32 bf16 + 16B pad) */
#define T_AH 0
#define T_AL 10240
#define T_BH 20480
#define T_BL 30720
#define T_SQ 40960         /* float[128] */

__global__ void __launch_bounds__(256) gemm_hmma_kernel(const float* __restrict__ bias,
                                                        float* __restrict__ out) {
    __shared__ __align__(16) char sm[40960 + 512];
    const int tid = threadIdx.x, lane = tid & 31, wid = tid >> 5;
    const int wm = wid >> 2, wn = wid & 3;     // warp grid 2 x 4
    const int m0 = blockIdx.x * 128;
    const uint32_t sbase = smem_u32(sm);

    if (tid < 128) *(float*)(sm + T_SQ + tid * 4) = 0.f;

    float acc[4][4][4];
#pragma unroll
    for (int a = 0; a < 4; a++)
#pragma unroll
        for (int b = 0; b < 4; b++)
#pragma unroll
            for (int c = 0; c < 4; c++) acc[a][b][c] = 0.f;

    // per-lane ldmatrix address components
    const int rowselA = lane & 15, khA = (lane >> 4) & 1;
    const uint32_t offA = (uint32_t)((wm * 64 + rowselA) * ROWB + khA * 16);
    const int bnB = lane & 7, khB = (lane >> 3) & 1;
    const uint32_t offB = (uint32_t)((wn * 32 + bnB) * ROWB + khB * 16);

    for (int kc = 0; kc < 8; kc++) {
        // ---- load 4 tiles of 128x32 bf16 ----
#pragma unroll
        for (int it = 0; it < 2; it++) {
            int i = tid + it * 256;            // 0..511
            int r = i >> 2, kq = i & 3;
            uint32_t soff = (uint32_t)(r * ROWB + kq * 16);
            size_t ga = (size_t)(m0 + r) * 256 + kc * 32 + kq * 8;
            size_t gb = (size_t)r * 256 + kc * 32 + kq * 8;
            *(uint4*)(sm + T_AH + soff) = *(const uint4*)(g_ah + ga);
            *(uint4*)(sm + T_AL + soff) = *(const uint4*)(g_al + ga);
            *(uint4*)(sm + T_BH + soff) = *(const uint4*)(g_Wh + gb);
            *(uint4*)(sm + T_BL + soff) = *(const uint4*)(g_Wl + gb);
        }
        __syncthreads();

#pragma unroll
        for (int s = 0; s < 2; s++) {
            uint32_t ah[4][4], al[4][4], bh[4][2], bl[4][2];
#pragma unroll
            for (int mi = 0; mi < 4; mi++) {
                uint32_t a = offA + (uint32_t)(mi * 16 * ROWB + s * 32);
                ldsm_x4(ah[mi], sbase + T_AH + a);
                ldsm_x4(al[mi], sbase + T_AL + a);
            }
#pragma unroll
            for (int nj = 0; nj < 4; nj++) {
                uint32_t b = offB + (uint32_t)(nj * 8 * ROWB + s * 32);
                ldsm_x2(bh[nj], sbase + T_BH + b);
                ldsm_x2(bl[nj], sbase + T_BL + b);
            }
#pragma unroll
            for (int mi = 0; mi < 4; mi++)
#pragma unroll
                for (int nj = 0; nj < 4; nj++) {
                    mma16816(acc[mi][nj], ah[mi], bh[nj]);
                    mma16816(acc[mi][nj], ah[mi], bl[nj]);
                    mma16816(acc[mi][nj], al[mi], bh[nj]);
                }
        }
        __syncthreads();
    }

    // ---- epilogue: + bias, row L2 norm, store ------------------------------
    const int groupl = lane >> 2, qid = lane & 3;
    float2 bv[4];
#pragma unroll
    for (int nj = 0; nj < 4; nj++)
        bv[nj] = *(const float2*)(bias + wn * 32 + nj * 8 + qid * 2);

    float* sq = (float*)(sm + T_SQ);
#pragma unroll
    for (int mi = 0; mi < 4; mi++) {
        float s1 = 0.f, s2 = 0.f;
#pragma unroll
        for (int nj = 0; nj < 4; nj++) {
            acc[mi][nj][0] += bv[nj].x;
            acc[mi][nj][1] += bv[nj].y;
            acc[mi][nj][2] += bv[nj].x;
            acc[mi][nj][3] += bv[nj].y;
            s1 += acc[mi][nj][0] * acc[mi][nj][0] + acc[mi][nj][1] * acc[mi][nj][1];
            s2 += acc[mi][nj][2] * acc[mi][nj][2] + acc[mi][nj][3] * acc[mi][nj][3];
        }
        s1 += __shfl_xor_sync(0xffffffffu, s1, 1);
        s1 += __shfl_xor_sync(0xffffffffu, s1, 2);
        s2 += __shfl_xor_sync(0xffffffffu, s2, 1);
        s2 += __shfl_xor_sync(0xffffffffu, s2, 2);
        if (qid == 0) {
            atomicAdd(&sq[wm * 64 + mi * 16 + groupl], s1);
            atomicAdd(&sq[wm * 64 + mi * 16 + groupl + 8], s2);
        }
    }
    __syncthreads();
    if (tid < 128) {
        float v = sq[tid];
        sq[tid] = 1.f / fmaxf(sqrtf(v), 1e-12f);
    }
    __syncthreads();

#pragma unroll
    for (int mi = 0; mi < 4; mi++) {
        int lr1 = wm * 64 + mi * 16 + groupl;
        int lr2 = lr1 + 8;
        float i1 = sq[lr1], i2 = sq[lr2];
        int r1 = m0 + lr1, r2 = m0 + lr2;
#pragma unroll
        for (int nj = 0; nj < 4; nj++) {
            int col = wn * 32 + nj * 8 + qid * 2;
            if (r1 < NN)
                *(float2*)(out + (size_t)r1 * 128 + col) =
                    make_float2(acc[mi][nj][0] * i1, acc[mi][nj][1] * i1);
            if (r2 < NN)
                *(float2*)(out + (size_t)r2 * 128 + col) =
                    make_float2(acc[mi][nj][2] * i2, acc[mi][nj][3] * i2);
        }
    }
}

// ---------------- launch ----------------------------------------------------
extern "C" void kernel_launch(void* const* d_in, const int* in_sizes, int n_in,
                              void* d_out, int out_size) {
    const float* x    = (const float*)d_in[0];
    const int*   ei   = (const int*)d_in[1];
    const float* W    = (const float*)d_in[2];
    const float* asrc = (const float*)d_in[3];
    const float* adst = (const float*)d_in[4];
    const float* bias = (const float*)d_in[5];
    float*       out  = (float*)d_out;

    void* xbuf_p = nullptr;
    cudaGetSymbolAddress(&xbuf_p, g_xbuf);
    float* xbuf = (float*)xbuf_p;

    zero_kernel<<<(NN + 255) / 256, 256>>>();
    hist_kernel<<<(EPE + 255) / 256, 256>>>(ei);
    scan_kernel<<<1, 1024>>>();
    scatter_kernel<<<(EPE + 255) / 256, 256>>>(ei);

    for (int l = 0; l < 2; l++) {
        const float* Wl  = W + (size_t)l * 128 * 256;
        const float* asl = asrc + (size_t)l * 256;
        const float* adl = adst + (size_t)l * 256;
        const float* bl  = bias + (size_t)l * 128;
        const float* xin = (l == 0) ? x : xbuf;
        float*       xo  = (l == 0) ? xbuf : out;

        prep_p_kernel<<<4, 128>>>(Wl, asl, adl);
        prep_w_kernel<<<128, 256>>>(Wl);
        alpha_kernel<<<(NN * 32 + 255) / 256, 256>>>(xin);
        aggregate_kernel<<<(NN * 32 + 255) / 256, 256>>>(xin);
        gemm_hmma_kernel<<<TILES, 256>>>(bl, xo);
    }
}